// round 5
// baseline (speedup 1.0000x reference)
#include <cuda_runtime.h>
#include <stdint.h>

// Output layout: fine_data [N*8, 64] f32, then fine_ijk [N*8, 3] written as f32
// (coords < 1024, exactly representable in f32).
//
// Fused kernel, 256 threads cover 64 coarse rows. Each thread:
//   - front-batches 4 independent float4 loads of coarse_data (MLP=4, coalesced
//     at stride 256 within the block) so reads hit DRAM in bursts,
//   - then writes each chunk to its 8 fine rows (32 float4 stores),
//   - threads also emit the fine_ijk region (64 rows * 24 floats = 384 float4
//     per block; thread t does q=t and, for t<128, q=t+256).

#define CHUNKS_PER_THREAD 4

__global__ void __launch_bounds__(256) upsample_fused_kernel(
    const float4* __restrict__ src,     // coarse_data as float4, N*16 elems
    const int* __restrict__ ijk,        // coarse_ijk, N*3 ints
    float4* __restrict__ dst_data,      // fine_data as float4
    float4* __restrict__ dst_ijk,       // fine_ijk region as float4
    int n)
{
    const int t   = threadIdx.x;
    const int bid = blockIdx.x;
    const int n16 = n * 16;

    // ---------- front-batched loads (MLP = 4) ----------
    int base_idx = bid * (256 * CHUNKS_PER_THREAD) + t;
    float4 v[CHUNKS_PER_THREAD];
    bool ok[CHUNKS_PER_THREAD];
#pragma unroll
    for (int i = 0; i < CHUNKS_PER_THREAD; i++) {
        int idx = base_idx + i * 256;
        ok[i] = (idx < n16);
        if (ok[i]) v[i] = __ldg(src + idx);
    }

    // ---------- ijk expansion (overlaps the load latency) ----------
    // Block covers coarse rows [bid*64, bid*64+64) -> 384 float4 of ijk output.
#pragma unroll
    for (int rep = 0; rep < 2; rep++) {
        int lt = t + rep * 256;
        if (lt < 384) {
            long long q = (long long)bid * 384 + lt;   // float4 index in ijk region
            if (q < (long long)n * 6) {
                long long e0 = q * 4;                  // first float element index
                float vals[4];
#pragma unroll
                for (int k = 0; k < 4; k++) {
                    long long e = e0 + k;
                    long long f = e / 3;               // fine voxel index
                    int comp    = (int)(e - f * 3);    // 0,1,2
                    long long cr = f >> 3;             // coarse row
                    int sub      = (int)(f & 7);       // sub-voxel 0..7
                    int c = __ldg(ijk + cr * 3 + comp);
                    int off = (sub >> (2 - comp)) & 1; // meshgrid ij order
                    vals[k] = (float)(2 * c + off);
                }
                dst_ijk[q] = make_float4(vals[0], vals[1], vals[2], vals[3]);
            }
        }
    }

    // ---------- data replication: long uninterrupted write run ----------
#pragma unroll
    for (int i = 0; i < CHUNKS_PER_THREAD; i++) {
        if (ok[i]) {
            int idx = base_idx + i * 256;
            int chunk = idx & 15;
            long long cr = idx >> 4;
            float4* base = dst_data + cr * 128 + chunk;  // 8 fine rows * 16 f4
#pragma unroll
            for (int j = 0; j < 8; j++) {
                base[j * 16] = v[i];
            }
        }
    }
}

extern "C" void kernel_launch(void* const* d_in, const int* in_sizes, int n_in,
                              void* d_out, int out_size) {
    const float* coarse_data = (const float*)d_in[0];
    const int*   coarse_ijk  = (const int*)d_in[1];
    float* out = (float*)d_out;

    int n = in_sizes[0] / 64;                       // coarse voxel count
    long long data_elems = (long long)n * 8 * 64;   // fine_data float count

    float4* dst_data = (float4*)out;
    float4* dst_ijk  = (float4*)(out + data_elems);

    long long f4 = (long long)n * 16;               // coarse float4 count
    int blocks = (int)((f4 + 1023) / 1024);         // 64 coarse rows per block
    upsample_fused_kernel<<<blocks, 256>>>((const float4*)coarse_data,
                                           coarse_ijk, dst_data, dst_ijk, n);
}

// round 6
// speedup vs baseline: 1.0120x; 1.0120x over previous
#include <cuda_runtime.h>
#include <stdint.h>

// Output layout: fine_data [N*8, 64] f32, then fine_ijk [N*8, 3] written as f32
// (coords < 1024, exactly representable in f32).
//
// Measured-best structure (R2): fused kernel, 256 threads cover 16 coarse rows.
//   - data: thread t -> coarse float4 idx = bid*256+t; one load, replicated to
//           the 8 fine rows (stride 64 floats). MLP_p1 = 1 (serial load->store)
//           which avoids cross-CTA L1tex-queue spread at high occupancy.
//   - ijk:  threads 0..95 each write one float4 of the ijk region
//           (16 rows * 24 floats = 96 float4 per block).
// DRAM-bound at ~6.1 TB/s (77% of spec); all other pipes <62%.

__global__ void __launch_bounds__(256) upsample_fused_kernel(
    const float4* __restrict__ src,     // coarse_data as float4, N*16 elems
    const int* __restrict__ ijk,        // coarse_ijk, N*3 ints
    float4* __restrict__ dst_data,      // fine_data as float4
    float4* __restrict__ dst_ijk,       // fine_ijk region as float4
    int n)
{
    const int t   = threadIdx.x;
    const int bid = blockIdx.x;

    // ---------- data replication ----------
    {
        int idx = bid * 256 + t;                 // coarse float4 index
        if (idx < n * 16) {
            int chunk = idx & 15;
            long long cr = idx >> 4;
            float4 v = src[idx];
            float4* base = dst_data + cr * 128 + chunk; // 8 fine rows * 16 f4
#pragma unroll
            for (int j = 0; j < 8; j++) {
                base[j * 16] = v;
            }
        }
    }

    // ---------- ijk expansion ----------
    // Block covers coarse rows [bid*16, bid*16+16) -> 96 float4 of ijk output.
    if (t < 96) {
        long long q = (long long)bid * 96 + t;      // float4 index in ijk region
        if (q < (long long)n * 6) {
            long long e0 = q * 4;                   // first float element index
            float vals[4];
#pragma unroll
            for (int k = 0; k < 4; k++) {
                long long e = e0 + k;
                long long f = e / 3;                // fine voxel index
                int comp    = (int)(e - f * 3);     // 0,1,2
                long long cr = f >> 3;              // coarse row
                int sub      = (int)(f & 7);        // sub-voxel 0..7
                int c = ijk[cr * 3 + comp];
                int off = (sub >> (2 - comp)) & 1;  // meshgrid ij order
                vals[k] = (float)(2 * c + off);
            }
            dst_ijk[q] = make_float4(vals[0], vals[1], vals[2], vals[3]);
        }
    }
}

extern "C" void kernel_launch(void* const* d_in, const int* in_sizes, int n_in,
                              void* d_out, int out_size) {
    const float* coarse_data = (const float*)d_in[0];
    const int*   coarse_ijk  = (const int*)d_in[1];
    float* out = (float*)d_out;

    int n = in_sizes[0] / 64;                       // coarse voxel count
    long long data_elems = (long long)n * 8 * 64;   // fine_data float count

    float4* dst_data = (float4*)out;
    float4* dst_ijk  = (float4*)(out + data_elems);

    int blocks = (n + 15) / 16;                     // 16 coarse rows per block
    upsample_fused_kernel<<<blocks, 256>>>((const float4*)coarse_data,
                                           coarse_ijk, dst_data, dst_ijk, n);
}

// round 7
// speedup vs baseline: 1.0291x; 1.0169x over previous
#include <cuda_runtime.h>
#include <stdint.h>

// Output layout: fine_data [N*8, 64] f32, then fine_ijk [N*8, 3] written as f32
// (coords < 1024, exactly representable in f32).
//
// CONVERGED structure (best of 6 rounds): fused kernel, 256 threads / 16
// coarse rows per block.
//   - data: thread t -> coarse float4 idx = bid*256+t; one load, replicated to
//           the 8 fine rows (stride 64 floats). MLP_p1 = 1 avoids cross-CTA
//           L1tex-queue spread at high occupancy (R5 showed MLP=4 regresses).
//   - ijk:  threads 0..95 each write one float4 of the ijk region
//           (16 rows * 24 floats = 96 float4 per block).
//
// Falsified levers (all within noise of this version, some worse):
//   R3 .cs evict-first hints; R4 256-bit ld/st; R5 front-batched MLP=4.
// App throughput ~6.7 TB/s (~84% of 8 TB/s HBM3e) on an 89%-write stream:
// memory roofline reached; traffic is mandatory (632 MB, no reuse available).

__global__ void __launch_bounds__(256) upsample_fused_kernel(
    const float4* __restrict__ src,     // coarse_data as float4, N*16 elems
    const int* __restrict__ ijk,        // coarse_ijk, N*3 ints
    float4* __restrict__ dst_data,      // fine_data as float4
    float4* __restrict__ dst_ijk,       // fine_ijk region as float4
    int n)
{
    const int t   = threadIdx.x;
    const int bid = blockIdx.x;

    // ---------- data replication ----------
    {
        int idx = bid * 256 + t;                 // coarse float4 index
        if (idx < n * 16) {
            int chunk = idx & 15;
            long long cr = idx >> 4;
            float4 v = src[idx];
            float4* base = dst_data + cr * 128 + chunk; // 8 fine rows * 16 f4
#pragma unroll
            for (int j = 0; j < 8; j++) {
                base[j * 16] = v;
            }
        }
    }

    // ---------- ijk expansion ----------
    // Block covers coarse rows [bid*16, bid*16+16) -> 96 float4 of ijk output.
    if (t < 96) {
        long long q = (long long)bid * 96 + t;      // float4 index in ijk region
        if (q < (long long)n * 6) {
            long long e0 = q * 4;                   // first float element index
            float vals[4];
#pragma unroll
            for (int k = 0; k < 4; k++) {
                long long e = e0 + k;
                long long f = e / 3;                // fine voxel index
                int comp    = (int)(e - f * 3);     // 0,1,2
                long long cr = f >> 3;              // coarse row
                int sub      = (int)(f & 7);        // sub-voxel 0..7
                int c = ijk[cr * 3 + comp];
                int off = (sub >> (2 - comp)) & 1;  // meshgrid ij order
                vals[k] = (float)(2 * c + off);
            }
            dst_ijk[q] = make_float4(vals[0], vals[1], vals[2], vals[3]);
        }
    }
}

extern "C" void kernel_launch(void* const* d_in, const int* in_sizes, int n_in,
                              void* d_out, int out_size) {
    const float* coarse_data = (const float*)d_in[0];
    const int*   coarse_ijk  = (const int*)d_in[1];
    float* out = (float*)d_out;

    int n = in_sizes[0] / 64;                       // coarse voxel count
    long long data_elems = (long long)n * 8 * 64;   // fine_data float count

    float4* dst_data = (float4*)out;
    float4* dst_ijk  = (float4*)(out + data_elems);

    int blocks = (n + 15) / 16;                     // 16 coarse rows per block
    upsample_fused_kernel<<<blocks, 256>>>((const float4*)coarse_data,
                                           coarse_ijk, dst_data, dst_ijk, n);
}

// round 8
// speedup vs baseline: 1.0298x; 1.0007x over previous
#include <cuda_runtime.h>
#include <stdint.h>

// Output layout: fine_data [N*8, 64] f32, then fine_ijk [N*8, 3] written as f32
// (coords < 1024, exactly representable in f32).
//
// CONVERGED (rounds 2-7): fused kernel, 256 threads / 16 coarse rows per block.
//   - data: thread t -> coarse float4 idx = bid*256+t; one load, replicated to
//           the 8 fine rows (stride 64 floats). MLP_p1 = 1 avoids cross-CTA
//           L1tex-queue spread at high occupancy (R5: MLP=4 regressed).
//   - ijk:  threads 0..95 each write one float4 of the ijk region
//           (16 rows * 24 floats = 96 float4 per block).
//
// Falsified levers (all within ±1.2us noise or worse):
//   R3 .cs evict-first; R4 256-bit ld/st; R5 front-batched MLP=4.
// Roofline: 632 MB mandatory traffic / 93.2us = 6.78 TB/s = 85% of HBM3e spec
// on an 89%-write stream. DRAM is the only saturated pipe; traffic is
// irreducible (no reuse exists in this op). Converged.

__global__ void __launch_bounds__(256) upsample_fused_kernel(
    const float4* __restrict__ src,     // coarse_data as float4, N*16 elems
    const int* __restrict__ ijk,        // coarse_ijk, N*3 ints
    float4* __restrict__ dst_data,      // fine_data as float4
    float4* __restrict__ dst_ijk,       // fine_ijk region as float4
    int n)
{
    const int t   = threadIdx.x;
    const int bid = blockIdx.x;

    // ---------- data replication ----------
    {
        int idx = bid * 256 + t;                 // coarse float4 index
        if (idx < n * 16) {
            int chunk = idx & 15;
            long long cr = idx >> 4;
            float4 v = src[idx];
            float4* base = dst_data + cr * 128 + chunk; // 8 fine rows * 16 f4
#pragma unroll
            for (int j = 0; j < 8; j++) {
                base[j * 16] = v;
            }
        }
    }

    // ---------- ijk expansion ----------
    // Block covers coarse rows [bid*16, bid*16+16) -> 96 float4 of ijk output.
    if (t < 96) {
        long long q = (long long)bid * 96 + t;      // float4 index in ijk region
        if (q < (long long)n * 6) {
            long long e0 = q * 4;                   // first float element index
            float vals[4];
#pragma unroll
            for (int k = 0; k < 4; k++) {
                long long e = e0 + k;
                long long f = e / 3;                // fine voxel index
                int comp    = (int)(e - f * 3);     // 0,1,2
                long long cr = f >> 3;              // coarse row
                int sub      = (int)(f & 7);        // sub-voxel 0..7
                int c = ijk[cr * 3 + comp];
                int off = (sub >> (2 - comp)) & 1;  // meshgrid ij order
                vals[k] = (float)(2 * c + off);
            }
            dst_ijk[q] = make_float4(vals[0], vals[1], vals[2], vals[3]);
        }
    }
}

extern "C" void kernel_launch(void* const* d_in, const int* in_sizes, int n_in,
                              void* d_out, int out_size) {
    const float* coarse_data = (const float*)d_in[0];
    const int*   coarse_ijk  = (const int*)d_in[1];
    float* out = (float*)d_out;

    int n = in_sizes[0] / 64;                       // coarse voxel count
    long long data_elems = (long long)n * 8 * 64;   // fine_data float count

    float4* dst_data = (float4*)out;
    float4* dst_ijk  = (float4*)(out + data_elems);

    int blocks = (n + 15) / 16;                     // 16 coarse rows per block
    upsample_fused_kernel<<<blocks, 256>>>((const float4*)coarse_data,
                                           coarse_ijk, dst_data, dst_ijk, n);
}